// round 9
// baseline (speedup 1.0000x reference)
#include <cuda_runtime.h>
#include <cuda_bf16.h>
#include <math.h>
#include <stdint.h>

#define NN 20000
#define EE 320000
#define TOTE (EE + NN)
#define HEADS 8
#define HID 32
#define OUTC 128
#define D0 256
#define D2 1024
#define NPART 79                 // ceil(NN/256)

// ---------------- scratch ---------------------------------------------------
__device__ float g_h[(size_t)NN * D2];
__device__ float g_feat[(size_t)NN * D0];
__device__ float g_res[(size_t)NN * D0];
__device__ float g_als[NN * HEADS];
__device__ float g_ald[NN * HEADS];
__device__ float g_alpha[(size_t)TOTE * HEADS];
__device__ int   g_deg[NN];
__device__ int   g_rowptr[NN + 1];
__device__ int   g_cursor[NN];
__device__ int   g_col[TOTE];
__device__ int   g_is32;
__device__ int   g_part[NPART];

// bf16 split operands (layers 0/1 activations, 256-wide)
__device__ __nv_bfloat16 g_ahi[(size_t)NN * D0];
__device__ __nv_bfloat16 g_alo[(size_t)NN * D0];
// layer-2 aggregated activations, 2048-wide (8 heads x 256)
__device__ __nv_bfloat16 g_ahi2[(size_t)NN * 2048];
__device__ __nv_bfloat16 g_alo2[(size_t)NN * 2048];
// folded attention weight vectors for layer 2: ws2[k*8+h] = W2[:,h,:]@as2[h]
__device__ float g_ws2[2048];
__device__ float g_wd2[2048];

#define WSZ 393216
#define OFF_W0  0u
#define OFF_RW0 16384u
#define OFF_W1  32768u
#define OFF_W2  98304u          // layer-2 blockdiag Wt: 128 rows x 2048 = 262144
#define OFF_RW2 360448u
__device__ __nv_bfloat16 g_whi[WSZ];
__device__ __nv_bfloat16 g_wlo[WSZ];

// ---------------- helpers ----------------------------------------------------
__device__ __forceinline__ uint32_t smem_u32(const void* p) {
    uint32_t r;
    asm("{ .reg .u64 t; cvta.to.shared.u64 t, %1; cvt.u32.u64 %0, t; }" : "=r"(r) : "l"(p));
    return r;
}

__device__ __forceinline__ void ldsm4(uint32_t* r, uint32_t addr) {
    asm volatile("ldmatrix.sync.aligned.m8n8.x4.shared.b16 {%0,%1,%2,%3}, [%4];"
                 : "=r"(r[0]), "=r"(r[1]), "=r"(r[2]), "=r"(r[3]) : "r"(addr));
}
__device__ __forceinline__ void ldsm2(uint32_t* r, uint32_t addr) {
    asm volatile("ldmatrix.sync.aligned.m8n8.x2.shared.b16 {%0,%1}, [%2];"
                 : "=r"(r[0]), "=r"(r[1]) : "r"(addr));
}
__device__ __forceinline__ void mma16816(float* c, const uint32_t* a, const uint32_t* b) {
    asm volatile("mma.sync.aligned.m16n8k16.row.col.f32.bf16.bf16.f32 "
                 "{%0,%1,%2,%3}, {%4,%5,%6,%7}, {%8,%9}, {%0,%1,%2,%3};"
                 : "+f"(c[0]), "+f"(c[1]), "+f"(c[2]), "+f"(c[3])
                 : "r"(a[0]), "r"(a[1]), "r"(a[2]), "r"(a[3]), "r"(b[0]), "r"(b[1]));
}

// ---------------- edge dtype detection -------------------------------------
__global__ void k_detect(const unsigned long long* __restrict__ p) {
    int i = blockIdx.x * blockDim.x + threadIdx.x;
    bool big = false;
    for (int j = i; j < EE; j += gridDim.x * blockDim.x)
        if (p[j] >= (unsigned long long)NN) big = true;
    if (__syncthreads_or(big) && threadIdx.x == 0) atomicOr(&g_is32, 1);
}

__device__ __forceinline__ int edge_at(const void* ei, int idx) {
    if (g_is32) return ((const int*)ei)[idx];
    return (int)((const long long*)ei)[idx];
}

// ---------------- CSR build -------------------------------------------------
__global__ void k_deg_init() {
    int i = blockIdx.x * blockDim.x + threadIdx.x;
    if (i < NN) g_deg[i] = 1;
    if (i == 0) g_is32 = 0;
}

__global__ void k_count(const void* __restrict__ ei) {
    int e = blockIdx.x * blockDim.x + threadIdx.x;
    if (e < EE) atomicAdd(&g_deg[edge_at(ei, EE + e)], 1);
}

__global__ void k_scanA() {
    __shared__ int sh[256];
    int i = blockIdx.x * 256 + threadIdx.x;
    sh[threadIdx.x] = (i < NN) ? g_deg[i] : 0;
    __syncthreads();
    for (int o = 128; o; o >>= 1) {
        if (threadIdx.x < o) sh[threadIdx.x] += sh[threadIdx.x + o];
        __syncthreads();
    }
    if (threadIdx.x == 0) g_part[blockIdx.x] = sh[0];
}

__global__ void k_scanB() {
    __shared__ int s[NPART];
    int t = threadIdx.x;
    if (t < NPART) s[t] = g_part[t];
    __syncthreads();
    if (t == 0) {
        int run = 0;
        for (int i = 0; i < NPART; i++) { int v = s[i]; s[i] = run; run += v; }
        g_rowptr[NN] = run;
    }
    __syncthreads();
    if (t < NPART) g_part[t] = s[t];
}

__global__ void k_scanC() {
    __shared__ int sh[256];
    int i = blockIdx.x * 256 + threadIdx.x;
    int v = (i < NN) ? g_deg[i] : 0;
    sh[threadIdx.x] = v;
    __syncthreads();
    for (int o = 1; o < 256; o <<= 1) {
        int a = (threadIdx.x >= o) ? sh[threadIdx.x - o] : 0;
        __syncthreads();
        sh[threadIdx.x] += a;
        __syncthreads();
    }
    if (i < NN) {
        int ex = sh[threadIdx.x] - v + g_part[blockIdx.x];
        g_rowptr[i] = ex;
        g_cursor[i] = ex;
    }
}

__global__ void k_fill(const void* __restrict__ ei) {
    int idx = blockIdx.x * blockDim.x + threadIdx.x;
    if (idx >= TOTE) return;
    int s, d;
    if (idx < EE) { s = edge_at(ei, idx); d = edge_at(ei, EE + idx); }
    else          { s = d = idx - EE; }
    int pos = atomicAdd(&g_cursor[d], 1);
    g_col[pos] = s;
}

// ---------------- bf16 split conversions ------------------------------------
__global__ void k_cvtA(const float* __restrict__ src, int Kt) {
    size_t idx = (size_t)blockIdx.x * blockDim.x + threadIdx.x;
    size_t tot = (size_t)NN * Kt;
    if (idx >= tot) return;
    float v = src[idx];
    __nv_bfloat16 hi = __float2bfloat16(v);
    g_ahi[idx] = hi;
    g_alo[idx] = __float2bfloat16(v - __bfloat162float(hi));
}

__global__ void k_cvtW(const float* __restrict__ W, unsigned woff, int K, int N) {
    int idx = blockIdx.x * blockDim.x + threadIdx.x;
    if (idx >= K * N) return;
    int k = idx / N, n = idx % N;
    float v = W[idx];
    __nv_bfloat16 hi = __float2bfloat16(v);
    g_whi[woff + (size_t)n * K + k] = hi;
    g_wlo[woff + (size_t)n * K + k] = __float2bfloat16(v - __bfloat162float(hi));
}

// layer-2 blockdiag weight: Wt2[c, h*256+k] = W2[k, h*128+c] / 8
__global__ void k_cvtW2(const float* __restrict__ W2) {
    int idx = blockIdx.x * blockDim.x + threadIdx.x;
    if (idx >= 128 * 2048) return;
    int c = idx >> 11, j = idx & 2047;
    int h = j >> 8, k = j & 255;
    float v = W2[(size_t)k * 1024 + h * 128 + c] * 0.125f;
    __nv_bfloat16 hi = __float2bfloat16(v);
    g_whi[OFF_W2 + idx] = hi;
    g_wlo[OFF_W2 + idx] = __float2bfloat16(v - __bfloat162float(hi));
}

// folded attention vectors: ws2[k*8+h] = sum_c W2[k, h*128+c]*as2[h,c]
__global__ void k_wsd2(const float* __restrict__ W2,
                       const float* __restrict__ as2, const float* __restrict__ ad2) {
    int idx = blockIdx.x * blockDim.x + threadIdx.x;
    if (idx >= 2048) return;
    int k = idx >> 3, h = idx & 7;
    const float* wp = W2 + (size_t)k * 1024 + h * 128;
    const float* sp = as2 + h * 128;
    const float* dp = ad2 + h * 128;
    float s = 0.f, d = 0.f;
    for (int c = 0; c < 128; c++) { float w = wp[c]; s += w * sp[c]; d += w * dp[c]; }
    g_ws2[idx] = s;
    g_wd2[idx] = d;
}

// ---------------- tensor-core GEMM via mma.sync (bf16 3-term split) ---------
// C[M,Nc] = A @ Wt^T.  A = (asel2? g_*2 : g_*) [M,Kt], Wt = whi+wlo [Nc,Kt].
// CTA tile 128(m) x 64(n), 8 warps 4x2, warp tile 32x32, K-chunk 32, reg prefetch.
#define RP 40

__global__ __launch_bounds__(256) void k_mma(int Kt, unsigned woff,
                                             const float* __restrict__ bias,
                                             int csel, int Nc, int asel2) {
    __shared__ __nv_bfloat16 sAh[128 * RP], sAl[128 * RP];
    __shared__ __nv_bfloat16 sBh[64 * RP],  sBl[64 * RP];

    const int tid = threadIdx.x, lane = tid & 31, wid = tid >> 5;
    const int m0 = (wid & 3) << 5;
    const int n0 = (wid >> 2) << 5;
    const int bm = blockIdx.y * 128, bn = blockIdx.x * 64;

    const uint32_t aAh = smem_u32(sAh), aAl = smem_u32(sAl);
    const uint32_t aBh = smem_u32(sBh), aBl = smem_u32(sBl);

    const __nv_bfloat16* GAh = asel2 ? g_ahi2 : g_ahi;
    const __nv_bfloat16* GAl = asel2 ? g_alo2 : g_alo;

    const int ar0 = tid >> 2, ac = (tid & 3) * 8;
    const int ar1 = (tid + 256) >> 2;
    const int br = tid >> 2;
    const int am0 = bm + ar0, am1 = bm + ar1;
    const size_t bb = (size_t)(bn + br) * Kt + ac;

    float acc[2][4][4] = {};
    uint4 pAh0, pAl0, pAh1, pAl1, pBh, pBl;
    const uint4 z4 = make_uint4(0, 0, 0, 0);

    pAh0 = (am0 < NN) ? *(const uint4*)(GAh + (size_t)am0 * Kt + ac) : z4;
    pAl0 = (am0 < NN) ? *(const uint4*)(GAl + (size_t)am0 * Kt + ac) : z4;
    pAh1 = (am1 < NN) ? *(const uint4*)(GAh + (size_t)am1 * Kt + ac) : z4;
    pAl1 = (am1 < NN) ? *(const uint4*)(GAl + (size_t)am1 * Kt + ac) : z4;
    pBh = *(const uint4*)(g_whi + woff + bb);
    pBl = *(const uint4*)(g_wlo + woff + bb);

    const int nch = Kt >> 5;
    for (int ch = 0; ch < nch; ch++) {
        *(uint4*)(sAh + ar0 * RP + ac) = pAh0;
        *(uint4*)(sAl + ar0 * RP + ac) = pAl0;
        *(uint4*)(sAh + ar1 * RP + ac) = pAh1;
        *(uint4*)(sAl + ar1 * RP + ac) = pAl1;
        *(uint4*)(sBh + br * RP + ac) = pBh;
        *(uint4*)(sBl + br * RP + ac) = pBl;
        __syncthreads();

        if (ch + 1 < nch) {
            const int k1 = (ch + 1) << 5;
            pAh0 = (am0 < NN) ? *(const uint4*)(GAh + (size_t)am0 * Kt + k1 + ac) : z4;
            pAl0 = (am0 < NN) ? *(const uint4*)(GAl + (size_t)am0 * Kt + k1 + ac) : z4;
            pAh1 = (am1 < NN) ? *(const uint4*)(GAh + (size_t)am1 * Kt + k1 + ac) : z4;
            pAl1 = (am1 < NN) ? *(const uint4*)(GAl + (size_t)am1 * Kt + k1 + ac) : z4;
            pBh = *(const uint4*)(g_whi + woff + bb + k1);
            pBl = *(const uint4*)(g_wlo + woff + bb + k1);
        }

#pragma unroll
        for (int ks = 0; ks < 32; ks += 16) {
            uint32_t ah[2][4], al[2][4], bh[4][2], bl[4][2];
#pragma unroll
            for (int mi = 0; mi < 2; mi++) {
                uint32_t off = (uint32_t)((m0 + mi * 16 + (lane & 15)) * RP
                                          + ks + ((lane >> 4) << 3)) * 2;
                ldsm4(ah[mi], aAh + off);
                ldsm4(al[mi], aAl + off);
            }
#pragma unroll
            for (int nj = 0; nj < 4; nj++) {
                uint32_t off = (uint32_t)((n0 + nj * 8 + (lane & 7)) * RP
                                          + ks + (((lane >> 3) & 1) << 3)) * 2;
                ldsm2(bh[nj], aBh + off);
                ldsm2(bl[nj], aBl + off);
            }
#pragma unroll
            for (int mi = 0; mi < 2; mi++)
#pragma unroll
                for (int nj = 0; nj < 4; nj++) {
                    mma16816(acc[mi][nj], ah[mi], bh[nj]);
                    mma16816(acc[mi][nj], ah[mi], bl[nj]);
                    mma16816(acc[mi][nj], al[mi], bh[nj]);
                }
        }
        __syncthreads();
    }

    float* C = csel ? (float*)g_res : (float*)g_h;
#pragma unroll
    for (int mi = 0; mi < 2; mi++) {
#pragma unroll
        for (int nj = 0; nj < 4; nj++) {
            int c = bn + n0 + nj * 8 + (lane & 3) * 2;
            float bx = 0.f, by = 0.f;
            if (bias) { bx = bias[c]; by = bias[c + 1]; }
            int r0 = bm + m0 + mi * 16 + (lane >> 2);
            if (r0 < NN) {
                float2 v = make_float2(acc[mi][nj][0] + bx, acc[mi][nj][1] + by);
                *(float2*)(C + (size_t)r0 * Nc + c) = v;
            }
            int r1 = r0 + 8;
            if (r1 < NN) {
                float2 v = make_float2(acc[mi][nj][2] + bx, acc[mi][nj][3] + by);
                *(float2*)(C + (size_t)r1 * Nc + c) = v;
            }
        }
    }
}

// ---------------- attention coefficients (layers 0/1, from g_h) -------------
__global__ void k_coef(const float* __restrict__ a_s, const float* __restrict__ a_d,
                       int D, int C) {
    int gw = (blockIdx.x * blockDim.x + threadIdx.x) >> 5;
    int lane = threadIdx.x & 31;
    if (gw >= NN * HEADS) return;
    int n = gw / HEADS, hd = gw % HEADS;
    const float* hp = g_h + (size_t)n * D + hd * C;
    const float* sp = a_s + hd * C;
    const float* dp = a_d + hd * C;
    float s = 0.f, d = 0.f;
    for (int c = lane; c < C; c += 32) {
        float v = hp[c];
        s += v * sp[c];
        d += v * dp[c];
    }
#pragma unroll
    for (int o = 16; o; o >>= 1) {
        s += __shfl_down_sync(0xffffffffu, s, o);
        d += __shfl_down_sync(0xffffffffu, d, o);
    }
    if (lane == 0) { g_als[gw] = s; g_ald[gw] = d; }
}

// ---------------- attention coefficients (layer 2, from feat + folded W) ----
// warp per node: als[n,h] = feat[n,:] . ws2[:,h]
__global__ void k_coef2() {
    int gw = (blockIdx.x * blockDim.x + threadIdx.x) >> 5;
    int lane = threadIdx.x & 31;
    if (gw >= NN) return;
    const float* fp = g_feat + (size_t)gw * D0;
    float s[8] = {}, d[8] = {};
#pragma unroll
    for (int i = 0; i < 8; i++) {
        int k = lane + 32 * i;
        float f = fp[k];
        const float4* wsp = (const float4*)(g_ws2 + k * 8);
        const float4* wdp = (const float4*)(g_wd2 + k * 8);
        float4 w0 = wsp[0], w1 = wsp[1], v0 = wdp[0], v1 = wdp[1];
        s[0] += f * w0.x; s[1] += f * w0.y; s[2] += f * w0.z; s[3] += f * w0.w;
        s[4] += f * w1.x; s[5] += f * w1.y; s[6] += f * w1.z; s[7] += f * w1.w;
        d[0] += f * v0.x; d[1] += f * v0.y; d[2] += f * v0.z; d[3] += f * v0.w;
        d[4] += f * v1.x; d[5] += f * v1.y; d[6] += f * v1.z; d[7] += f * v1.w;
    }
#pragma unroll
    for (int h = 0; h < 8; h++) {
#pragma unroll
        for (int o = 16; o; o >>= 1) {
            s[h] += __shfl_down_sync(0xffffffffu, s[h], o);
            d[h] += __shfl_down_sync(0xffffffffu, d[h], o);
        }
    }
    if (lane == 0) {
#pragma unroll
        for (int h = 0; h < 8; h++) { g_als[gw * 8 + h] = s[h]; g_ald[gw * 8 + h] = d[h]; }
    }
}

// ---------------- softmax over incoming edges (per node,head) --------------
__global__ void k_alpha() {
    int t = blockIdx.x * blockDim.x + threadIdx.x;
    if (t >= NN * HEADS) return;
    int n = t / HEADS, h = t % HEADS;
    int b = g_rowptr[n], e = g_rowptr[n + 1];
    float ad = g_ald[n * HEADS + h];
    float mx = -INFINITY;
    for (int j = b; j < e; j++) {
        float v = g_als[g_col[j] * HEADS + h] + ad;
        v = v > 0.f ? v : 0.2f * v;
        g_alpha[(size_t)j * HEADS + h] = v;
        mx = fmaxf(mx, v);
    }
    float den = 0.f;
    for (int j = b; j < e; j++) {
        float ex = expf(g_alpha[(size_t)j * HEADS + h] - mx);
        g_alpha[(size_t)j * HEADS + h] = ex;
        den += ex;
    }
    float inv = 1.f / (den + 1e-16f);
    for (int j = b; j < e; j++) g_alpha[(size_t)j * HEADS + h] *= inv;
}

// ---------------- aggregate + LN + residual + ELU (layers 0/1) --------------
__global__ void k_agg01(const float* __restrict__ bias,
                        const float* __restrict__ lng, const float* __restrict__ lnb,
                        int resmode, const float* __restrict__ rw) {
    __shared__ float red[17];
    int n = blockIdx.x;
    int t = threadIdx.x;
    int b = g_rowptr[n], e = g_rowptr[n + 1];
    int hd = t >> 5;
    float acc = 0.f;
    for (int j = b; j < e; j++) {
        float a = g_alpha[(size_t)j * HEADS + hd];
        acc += a * g_h[(size_t)g_col[j] * D0 + t];
    }
    float v = acc + bias[t];
    float s = v, q = v * v;
#pragma unroll
    for (int o = 16; o; o >>= 1) {
        s += __shfl_down_sync(0xffffffffu, s, o);
        q += __shfl_down_sync(0xffffffffu, q, o);
    }
    int w = t >> 5, lane = t & 31;
    if (lane == 0) { red[w] = s; red[8 + w] = q; }
    __syncthreads();
    if (t == 0) {
        float S = 0.f, Q = 0.f;
        for (int i = 0; i < 8; i++) { S += red[i]; Q += red[8 + i]; }
        red[0] = S; red[8] = Q;
    }
    __syncthreads();
    float mu = red[0] * (1.f / 256.f);
    float var = red[8] * (1.f / 256.f) - mu * mu;
    float ln = (v - mu) * rsqrtf(var + 1e-5f) * lng[t] + lnb[t];
    float sg = 1.f / (1.f + expf(-rw[0]));
    float rv = resmode ? g_feat[(size_t)n * D0 + t] : g_res[(size_t)n * D0 + t];
    float o = ln + sg * rv;
    __syncthreads();
    float ov = o > 0.f ? o : expm1f(o);
    size_t idx = (size_t)n * D0 + t;
    g_feat[idx] = ov;
    __nv_bfloat16 hi = __float2bfloat16(ov);
    g_ahi[idx] = hi;
    g_alo[idx] = __float2bfloat16(ov - __bfloat162float(hi));
}

// ---------------- layer-2 feature aggregation (per head, pre-GEMM) ----------
// agg[n, h*256 + t] = sum_e alpha[e,h] * feat[src_e, t]; emitted as bf16 split.
__global__ void k_aggF() {
    int n = blockIdx.x, t = threadIdx.x;
    int b = g_rowptr[n], e = g_rowptr[n + 1];
    float acc[8] = {};
    for (int j = b; j < e; j++) {
        float f = g_feat[(size_t)g_col[j] * D0 + t];
        const float4* ap = (const float4*)(g_alpha + (size_t)j * HEADS);
        float4 a0 = ap[0], a1 = ap[1];
        acc[0] += a0.x * f; acc[1] += a0.y * f; acc[2] += a0.z * f; acc[3] += a0.w * f;
        acc[4] += a1.x * f; acc[5] += a1.y * f; acc[6] += a1.z * f; acc[7] += a1.w * f;
    }
    size_t base = (size_t)n * 2048 + t;
#pragma unroll
    for (int h = 0; h < 8; h++) {
        __nv_bfloat16 hi = __float2bfloat16(acc[h]);
        g_ahi2[base + h * 256] = hi;
        g_alo2[base + h * 256] = __float2bfloat16(acc[h] - __bfloat162float(hi));
    }
}

// ---------------- layer-2 LN epilogue ----------------------------------------
__global__ void k_ln2(const float* __restrict__ b2,
                      const float* __restrict__ lng, const float* __restrict__ lnb,
                      const float* __restrict__ rw, float* __restrict__ out) {
    __shared__ float red[9];
    int n = blockIdx.x;
    int c = threadIdx.x;   // 0..127
    float v = g_h[(size_t)n * OUTC + c] + b2[c];
    float s = v, q = v * v;
#pragma unroll
    for (int o = 16; o; o >>= 1) {
        s += __shfl_down_sync(0xffffffffu, s, o);
        q += __shfl_down_sync(0xffffffffu, q, o);
    }
    int w = c >> 5, lane = c & 31;
    if (lane == 0) { red[w] = s; red[4 + w] = q; }
    __syncthreads();
    if (c == 0) {
        float S = 0.f, Q = 0.f;
        for (int i = 0; i < 4; i++) { S += red[i]; Q += red[4 + i]; }
        red[0] = S; red[4] = Q;
    }
    __syncthreads();
    float mu = red[0] * (1.f / 128.f);
    float var = red[4] * (1.f / 128.f) - mu * mu;
    float ln = (v - mu) * rsqrtf(var + 1e-5f) * lng[c] + lnb[c];
    float sg = 1.f / (1.f + expf(-rw[0]));
    out[(size_t)n * OUTC + c] = ln + sg * g_res[(size_t)n * OUTC + c];
}

// ---------------------------------------------------------------------------
extern "C" void kernel_launch(void* const* d_in, const int* in_sizes, int n_in,
                              void* d_out, int out_size) {
    const float* x    = (const float*)d_in[0];
    const void*  ei   = d_in[1];
    const float* W0  = (const float*)d_in[2];
    const float* b0  = (const float*)d_in[3];
    const float* as0 = (const float*)d_in[4];
    const float* ad0 = (const float*)d_in[5];
    const float* lng0 = (const float*)d_in[6];
    const float* lnb0 = (const float*)d_in[7];
    const float* rW0 = (const float*)d_in[8];
    const float* rb0 = (const float*)d_in[9];
    const float* rw0 = (const float*)d_in[10];
    const float* W1  = (const float*)d_in[11];
    const float* b1  = (const float*)d_in[12];
    const float* as1 = (const float*)d_in[13];
    const float* ad1 = (const float*)d_in[14];
    const float* lng1 = (const float*)d_in[15];
    const float* lnb1 = (const float*)d_in[16];
    const float* rw1 = (const float*)d_in[17];
    const float* W2  = (const float*)d_in[18];
    const float* b2  = (const float*)d_in[19];
    const float* as2 = (const float*)d_in[20];
    const float* ad2 = (const float*)d_in[21];
    const float* lng2 = (const float*)d_in[22];
    const float* lnb2 = (const float*)d_in[23];
    const float* rW2 = (const float*)d_in[24];
    const float* rb2 = (const float*)d_in[25];
    const float* rw2 = (const float*)d_in[26];
    float* out = (float*)d_out;

    // ---- CSR build ----
    k_deg_init<<<(NN + 255) / 256, 256>>>();
    k_detect<<<256, 256>>>((const unsigned long long*)ei);
    k_count<<<(EE + 255) / 256, 256>>>(ei);
    k_scanA<<<NPART, 256>>>();
    k_scanB<<<1, 128>>>();
    k_scanC<<<NPART, 256>>>();
    k_fill<<<(TOTE + 255) / 256, 256>>>(ei);

    // ---- weight prep ----
    k_cvtW<<<(64 * 256 + 255) / 256, 256>>>(W0,  OFF_W0,  64, 256);
    k_cvtW<<<(64 * 256 + 255) / 256, 256>>>(rW0, OFF_RW0, 64, 256);
    k_cvtW<<<(256 * 256 + 255) / 256, 256>>>(W1, OFF_W1, 256, 256);
    k_cvtW2<<<(128 * 2048 + 255) / 256, 256>>>(W2);
    k_cvtW<<<(256 * 128 + 255) / 256, 256>>>(rW2, OFF_RW2, 256, 128);
    k_wsd2<<<8, 256>>>(W2, as2, ad2);

    const int GY = (NN + 127) / 128;   // 157

    // ---- layer 0 ----
    k_cvtA<<<(NN * 64 + 255) / 256, 256>>>(x, 64);
    k_mma<<<dim3(4, GY), 256>>>(64, OFF_W0,  nullptr, 0, 256, 0);
    k_mma<<<dim3(4, GY), 256>>>(64, OFF_RW0, rb0,     1, 256, 0);
    k_coef<<<(NN * HEADS * 32 + 255) / 256, 256>>>(as0, ad0, D0, HID);
    k_alpha<<<(NN * HEADS + 255) / 256, 256>>>();
    k_agg01<<<NN, 256>>>(b0, lng0, lnb0, 0, rw0);

    // ---- layer 1 ----
    k_mma<<<dim3(4, GY), 256>>>(256, OFF_W1, nullptr, 0, 256, 0);
    k_coef<<<(NN * HEADS * 32 + 255) / 256, 256>>>(as1, ad1, D0, HID);
    k_alpha<<<(NN * HEADS + 255) / 256, 256>>>();
    k_agg01<<<NN, 256>>>(b1, lng1, lnb1, 1, rw1);

    // ---- layer 2 (aggregate-then-project) ----
    k_mma<<<dim3(2, GY), 256>>>(256, OFF_RW2, rb2, 1, 128, 0);   // residual -> g_res
    k_coef2<<<(NN * 32 + 255) / 256, 256>>>();
    k_alpha<<<(NN * HEADS + 255) / 256, 256>>>();
    k_aggF<<<NN, 256>>>();                                        // -> g_ahi2/g_alo2
    k_mma<<<dim3(2, GY), 256>>>(2048, OFF_W2, nullptr, 0, 128, 1); // -> g_h [N,128]
    k_ln2<<<NN, 128>>>(b2, lng2, lnb2, rw2, out);
}

// round 14
// speedup vs baseline: 1.2114x; 1.2114x over previous
#include <cuda_runtime.h>
#include <cuda_bf16.h>
#include <math.h>
#include <stdint.h>

#define NN 20000
#define EE 320000
#define TOTE (EE + NN)
#define HEADS 8
#define HID 32
#define OUTC 128
#define D0 256
#define D2 1024
#define NPART 79                 // ceil(NN/256)

// ---------------- scratch ---------------------------------------------------
__device__ float g_h[(size_t)NN * D2];
__device__ float g_feat[(size_t)NN * D0];
__device__ float g_res[(size_t)NN * D0];
__device__ float g_als[NN * HEADS];
__device__ float g_ald[NN * HEADS];
__device__ float g_alpha[(size_t)TOTE * HEADS];
__device__ int   g_deg[NN];
__device__ int   g_rowptr[NN + 1];
__device__ int   g_cursor[NN];
__device__ int   g_col[TOTE];
__device__ int   g_is32;
__device__ int   g_part[NPART];

// bf16 split operands
__device__ __nv_bfloat16 g_ahi[(size_t)NN * D0];
__device__ __nv_bfloat16 g_alo[(size_t)NN * D0];
#define WSZ 393216
#define OFF_W0  0u            // 512 rows x 64  (W0 cols 0-255, rW0 cols 256-511)
#define OFF_RW0 16384u
#define OFF_W1  32768u        // 256 rows x 256
#define OFF_W2  98304u        // 1152 rows x 256 (W2 cols 0-1023, rW2 cols 1024-1151)
#define OFF_RW2 360448u
__device__ __nv_bfloat16 g_whi[WSZ];
__device__ __nv_bfloat16 g_wlo[WSZ];

// ---------------- helpers ----------------------------------------------------
__device__ __forceinline__ uint32_t smem_u32(const void* p) {
    uint32_t r;
    asm("{ .reg .u64 t; cvta.to.shared.u64 t, %1; cvt.u32.u64 %0, t; }" : "=r"(r) : "l"(p));
    return r;
}

__device__ __forceinline__ void ldsm4(uint32_t* r, uint32_t addr) {
    asm volatile("ldmatrix.sync.aligned.m8n8.x4.shared.b16 {%0,%1,%2,%3}, [%4];"
                 : "=r"(r[0]), "=r"(r[1]), "=r"(r[2]), "=r"(r[3]) : "r"(addr));
}
__device__ __forceinline__ void ldsm2(uint32_t* r, uint32_t addr) {
    asm volatile("ldmatrix.sync.aligned.m8n8.x2.shared.b16 {%0,%1}, [%2];"
                 : "=r"(r[0]), "=r"(r[1]) : "r"(addr));
}
__device__ __forceinline__ void mma16816(float* c, const uint32_t* a, const uint32_t* b) {
    asm volatile("mma.sync.aligned.m16n8k16.row.col.f32.bf16.bf16.f32 "
                 "{%0,%1,%2,%3}, {%4,%5,%6,%7}, {%8,%9}, {%0,%1,%2,%3};"
                 : "+f"(c[0]), "+f"(c[1]), "+f"(c[2]), "+f"(c[3])
                 : "r"(a[0]), "r"(a[1]), "r"(a[2]), "r"(a[3]), "r"(b[0]), "r"(b[1]));
}

// ---------------- edge dtype detection -------------------------------------
__global__ void k_detect(const unsigned long long* __restrict__ p) {
    int i = blockIdx.x * blockDim.x + threadIdx.x;
    bool big = false;
    for (int j = i; j < EE; j += gridDim.x * blockDim.x)
        if (p[j] >= (unsigned long long)NN) big = true;
    if (__syncthreads_or(big) && threadIdx.x == 0) atomicOr(&g_is32, 1);
}

__device__ __forceinline__ int edge_at(const void* ei, int idx) {
    if (g_is32) return ((const int*)ei)[idx];
    return (int)((const long long*)ei)[idx];
}

// ---------------- CSR build -------------------------------------------------
__global__ void k_deg_init() {
    int i = blockIdx.x * blockDim.x + threadIdx.x;
    if (i < NN) g_deg[i] = 1;
    if (i == 0) g_is32 = 0;
}

__global__ void k_count(const void* __restrict__ ei) {
    int e = blockIdx.x * blockDim.x + threadIdx.x;
    if (e < EE) atomicAdd(&g_deg[edge_at(ei, EE + e)], 1);
}

__global__ void k_scanA() {
    __shared__ int sh[256];
    int i = blockIdx.x * 256 + threadIdx.x;
    sh[threadIdx.x] = (i < NN) ? g_deg[i] : 0;
    __syncthreads();
    for (int o = 128; o; o >>= 1) {
        if (threadIdx.x < o) sh[threadIdx.x] += sh[threadIdx.x + o];
        __syncthreads();
    }
    if (threadIdx.x == 0) g_part[blockIdx.x] = sh[0];
}

__global__ void k_scanB() {
    __shared__ int s[NPART];
    int t = threadIdx.x;
    if (t < NPART) s[t] = g_part[t];
    __syncthreads();
    if (t == 0) {
        int run = 0;
        for (int i = 0; i < NPART; i++) { int v = s[i]; s[i] = run; run += v; }
        g_rowptr[NN] = run;
    }
    __syncthreads();
    if (t < NPART) g_part[t] = s[t];
}

__global__ void k_scanC() {
    __shared__ int sh[256];
    int i = blockIdx.x * 256 + threadIdx.x;
    int v = (i < NN) ? g_deg[i] : 0;
    sh[threadIdx.x] = v;
    __syncthreads();
    for (int o = 1; o < 256; o <<= 1) {
        int a = (threadIdx.x >= o) ? sh[threadIdx.x - o] : 0;
        __syncthreads();
        sh[threadIdx.x] += a;
        __syncthreads();
    }
    if (i < NN) {
        int ex = sh[threadIdx.x] - v + g_part[blockIdx.x];
        g_rowptr[i] = ex;
        g_cursor[i] = ex;
    }
}

__global__ void k_fill(const void* __restrict__ ei) {
    int idx = blockIdx.x * blockDim.x + threadIdx.x;
    if (idx >= TOTE) return;
    int s, d;
    if (idx < EE) { s = edge_at(ei, idx); d = edge_at(ei, EE + idx); }
    else          { s = d = idx - EE; }
    int pos = atomicAdd(&g_cursor[d], 1);
    g_col[pos] = s;
}

// ---------------- bf16 split conversions ------------------------------------
__global__ void k_cvtA(const float* __restrict__ src, int Kt) {
    size_t idx = (size_t)blockIdx.x * blockDim.x + threadIdx.x;
    size_t tot = (size_t)NN * Kt;
    if (idx >= tot) return;
    float v = src[idx];
    __nv_bfloat16 hi = __float2bfloat16(v);
    g_ahi[idx] = hi;
    g_alo[idx] = __float2bfloat16(v - __bfloat162float(hi));
}

__global__ void k_cvtW(const float* __restrict__ W, unsigned woff, int K, int N) {
    int idx = blockIdx.x * blockDim.x + threadIdx.x;
    if (idx >= K * N) return;
    int k = idx / N, n = idx % N;
    float v = W[idx];
    __nv_bfloat16 hi = __float2bfloat16(v);
    g_whi[woff + (size_t)n * K + k] = hi;
    g_wlo[woff + (size_t)n * K + k] = __float2bfloat16(v - __bfloat162float(hi));
}

// ---------------- tensor-core GEMM via mma.sync (bf16 3-term split) ---------
// C cols [0,split) -> g_h (row stride strideH), no bias; optionally fused
// attention-coef reduction (fuse=1, heads of 32 cols).
// C cols [split,..) -> g_res (row stride strideR) + bias.
// CTA tile 128(m) x 64(n), 8 warps 4x2, warp tile 32x32, K-chunk 32, reg prefetch.
#define RP 40

__global__ __launch_bounds__(256) void k_mma(int Kt, unsigned woff,
                                             const float* __restrict__ bias,
                                             int split, int strideH, int strideR,
                                             int fuse,
                                             const float* __restrict__ a_s,
                                             const float* __restrict__ a_d) {
    __shared__ __nv_bfloat16 sAh[128 * RP], sAl[128 * RP];
    __shared__ __nv_bfloat16 sBh[64 * RP],  sBl[64 * RP];
    __shared__ float sAS[256], sAD[256];

    const int tid = threadIdx.x, lane = tid & 31, wid = tid >> 5;
    const int m0 = (wid & 3) << 5;
    const int n0 = (wid >> 2) << 5;
    const int bm = blockIdx.y * 128, bn = blockIdx.x * 64;

    const uint32_t aAh = smem_u32(sAh), aAl = smem_u32(sAl);
    const uint32_t aBh = smem_u32(sBh), aBl = smem_u32(sBl);

    if (fuse) { sAS[tid] = a_s[tid]; sAD[tid] = a_d[tid]; }

    const int ar0 = tid >> 2, ac = (tid & 3) * 8;
    const int ar1 = (tid + 256) >> 2;
    const int br = tid >> 2;
    const int am0 = bm + ar0, am1 = bm + ar1;
    const size_t bb = (size_t)(bn + br) * Kt + ac;

    float acc[2][4][4] = {};
    uint4 pAh0, pAl0, pAh1, pAl1, pBh, pBl;
    const uint4 z4 = make_uint4(0, 0, 0, 0);

    pAh0 = (am0 < NN) ? *(const uint4*)(g_ahi + (size_t)am0 * Kt + ac) : z4;
    pAl0 = (am0 < NN) ? *(const uint4*)(g_alo + (size_t)am0 * Kt + ac) : z4;
    pAh1 = (am1 < NN) ? *(const uint4*)(g_ahi + (size_t)am1 * Kt + ac) : z4;
    pAl1 = (am1 < NN) ? *(const uint4*)(g_alo + (size_t)am1 * Kt + ac) : z4;
    pBh = *(const uint4*)(g_whi + woff + bb);
    pBl = *(const uint4*)(g_wlo + woff + bb);

    const int nch = Kt >> 5;
    for (int ch = 0; ch < nch; ch++) {
        *(uint4*)(sAh + ar0 * RP + ac) = pAh0;
        *(uint4*)(sAl + ar0 * RP + ac) = pAl0;
        *(uint4*)(sAh + ar1 * RP + ac) = pAh1;
        *(uint4*)(sAl + ar1 * RP + ac) = pAl1;
        *(uint4*)(sBh + br * RP + ac) = pBh;
        *(uint4*)(sBl + br * RP + ac) = pBl;
        __syncthreads();

        if (ch + 1 < nch) {
            const int k1 = (ch + 1) << 5;
            pAh0 = (am0 < NN) ? *(const uint4*)(g_ahi + (size_t)am0 * Kt + k1 + ac) : z4;
            pAl0 = (am0 < NN) ? *(const uint4*)(g_alo + (size_t)am0 * Kt + k1 + ac) : z4;
            pAh1 = (am1 < NN) ? *(const uint4*)(g_ahi + (size_t)am1 * Kt + k1 + ac) : z4;
            pAl1 = (am1 < NN) ? *(const uint4*)(g_alo + (size_t)am1 * Kt + k1 + ac) : z4;
            pBh = *(const uint4*)(g_whi + woff + bb + k1);
            pBl = *(const uint4*)(g_wlo + woff + bb + k1);
        }

#pragma unroll
        for (int ks = 0; ks < 32; ks += 16) {
            uint32_t ah[2][4], al[2][4], bh[4][2], bl[4][2];
#pragma unroll
            for (int mi = 0; mi < 2; mi++) {
                uint32_t off = (uint32_t)((m0 + mi * 16 + (lane & 15)) * RP
                                          + ks + ((lane >> 4) << 3)) * 2;
                ldsm4(ah[mi], aAh + off);
                ldsm4(al[mi], aAl + off);
            }
#pragma unroll
            for (int nj = 0; nj < 4; nj++) {
                uint32_t off = (uint32_t)((n0 + nj * 8 + (lane & 7)) * RP
                                          + ks + (((lane >> 3) & 1) << 3)) * 2;
                ldsm2(bh[nj], aBh + off);
                ldsm2(bl[nj], aBl + off);
            }
#pragma unroll
            for (int mi = 0; mi < 2; mi++)
#pragma unroll
                for (int nj = 0; nj < 4; nj++) {
                    mma16816(acc[mi][nj], ah[mi], bh[nj]);
                    mma16816(acc[mi][nj], ah[mi], bl[nj]);
                    mma16816(acc[mi][nj], al[mi], bh[nj]);
                }
        }
        __syncthreads();
    }

    // ---- epilogue ----
    const int wcol = bn + n0;            // warp's 32-col block start (32-aligned)
    const int side = wcol < split;       // 1 => g_h (+ optional coef)
    const int hd = wcol >> 5;
    const int rbase = bm + m0 + (lane >> 2);
    float sPs[4] = {}, sPd[4] = {};

#pragma unroll
    for (int mi = 0; mi < 2; mi++) {
#pragma unroll
        for (int nj = 0; nj < 4; nj++) {
            int cg = wcol + nj * 8 + (lane & 3) * 2;
            int r0 = rbase + mi * 16, r1 = r0 + 8;
            float v0 = acc[mi][nj][0], v1 = acc[mi][nj][1];
            float v2 = acc[mi][nj][2], v3 = acc[mi][nj][3];
            if (side) {
                if (r0 < NN) *(float2*)(g_h + (size_t)r0 * strideH + cg) = make_float2(v0, v1);
                if (r1 < NN) *(float2*)(g_h + (size_t)r1 * strideH + cg) = make_float2(v2, v3);
                if (fuse) {
                    int cc = (hd << 5) | (cg & 31);
                    float as0 = sAS[cc], as1 = sAS[cc + 1];
                    float ad0 = sAD[cc], ad1 = sAD[cc + 1];
                    sPs[mi * 2 + 0] += v0 * as0 + v1 * as1;
                    sPs[mi * 2 + 1] += v2 * as0 + v3 * as1;
                    sPd[mi * 2 + 0] += v0 * ad0 + v1 * ad1;
                    sPd[mi * 2 + 1] += v2 * ad0 + v3 * ad1;
                }
            } else {
                int cr = cg - split;
                float bx = bias ? bias[cr] : 0.f;
                float by = bias ? bias[cr + 1] : 0.f;
                if (r0 < NN) *(float2*)(g_res + (size_t)r0 * strideR + cr) = make_float2(v0 + bx, v1 + by);
                if (r1 < NN) *(float2*)(g_res + (size_t)r1 * strideR + cr) = make_float2(v2 + bx, v3 + by);
            }
        }
    }

    if (side && fuse) {
#pragma unroll
        for (int q = 0; q < 4; q++) {
            sPs[q] += __shfl_xor_sync(0xffffffffu, sPs[q], 1);
            sPs[q] += __shfl_xor_sync(0xffffffffu, sPs[q], 2);
            sPd[q] += __shfl_xor_sync(0xffffffffu, sPd[q], 1);
            sPd[q] += __shfl_xor_sync(0xffffffffu, sPd[q], 2);
        }
        if ((lane & 3) == 0) {
#pragma unroll
            for (int q = 0; q < 4; q++) {
                int r = rbase + (q >> 1) * 16 + (q & 1) * 8;
                if (r < NN) {
                    g_als[r * 8 + hd] = sPs[q];
                    g_ald[r * 8 + hd] = sPd[q];
                }
            }
        }
    }
}

// ---------------- attention coefficients (layer 2, from g_h) ----------------
__global__ void k_coef(const float* __restrict__ a_s, const float* __restrict__ a_d,
                       int D, int C) {
    int gw = (blockIdx.x * blockDim.x + threadIdx.x) >> 5;
    int lane = threadIdx.x & 31;
    if (gw >= NN * HEADS) return;
    int n = gw / HEADS, hd = gw % HEADS;
    const float* hp = g_h + (size_t)n * D + hd * C;
    const float* sp = a_s + hd * C;
    const float* dp = a_d + hd * C;
    float s = 0.f, d = 0.f;
    for (int c = lane; c < C; c += 32) {
        float v = hp[c];
        s += v * sp[c];
        d += v * dp[c];
    }
#pragma unroll
    for (int o = 16; o; o >>= 1) {
        s += __shfl_down_sync(0xffffffffu, s, o);
        d += __shfl_down_sync(0xffffffffu, d, o);
    }
    if (lane == 0) { g_als[gw] = s; g_ald[gw] = d; }
}

// ---------------- softmax over incoming edges (per node,head) --------------
__global__ void k_alpha() {
    int t = blockIdx.x * blockDim.x + threadIdx.x;
    if (t >= NN * HEADS) return;
    int n = t / HEADS, h = t % HEADS;
    int b = g_rowptr[n], e = g_rowptr[n + 1];
    float ad = g_ald[n * HEADS + h];
    float mx = -INFINITY;
    for (int j = b; j < e; j++) {
        float v = g_als[g_col[j] * HEADS + h] + ad;
        v = v > 0.f ? v : 0.2f * v;
        g_alpha[(size_t)j * HEADS + h] = v;
        mx = fmaxf(mx, v);
    }
    float den = 0.f;
    for (int j = b; j < e; j++) {
        float ex = expf(g_alpha[(size_t)j * HEADS + h] - mx);
        g_alpha[(size_t)j * HEADS + h] = ex;
        den += ex;
    }
    float inv = 1.f / (den + 1e-16f);
    for (int j = b; j < e; j++) g_alpha[(size_t)j * HEADS + h] *= inv;
}

// ---------------- aggregate + LN + residual + ELU (layers 0/1) --------------
__global__ void k_agg01(const float* __restrict__ bias,
                        const float* __restrict__ lng, const float* __restrict__ lnb,
                        int resmode, const float* __restrict__ rw) {
    __shared__ float red[17];
    int n = blockIdx.x;
    int t = threadIdx.x;
    int b = g_rowptr[n], e = g_rowptr[n + 1];
    int hd = t >> 5;
    float acc = 0.f;
    for (int j = b; j < e; j++) {
        float a = g_alpha[(size_t)j * HEADS + hd];
        acc += a * g_h[(size_t)g_col[j] * D0 + t];
    }
    float v = acc + bias[t];
    float s = v, q = v * v;
#pragma unroll
    for (int o = 16; o; o >>= 1) {
        s += __shfl_down_sync(0xffffffffu, s, o);
        q += __shfl_down_sync(0xffffffffu, q, o);
    }
    int w = t >> 5, lane = t & 31;
    if (lane == 0) { red[w] = s; red[8 + w] = q; }
    __syncthreads();
    if (t == 0) {
        float S = 0.f, Q = 0.f;
        for (int i = 0; i < 8; i++) { S += red[i]; Q += red[8 + i]; }
        red[0] = S; red[8] = Q;
    }
    __syncthreads();
    float mu = red[0] * (1.f / 256.f);
    float var = red[8] * (1.f / 256.f) - mu * mu;
    float ln = (v - mu) * rsqrtf(var + 1e-5f) * lng[t] + lnb[t];
    float sg = 1.f / (1.f + expf(-rw[0]));
    float rv = resmode ? g_feat[(size_t)n * D0 + t] : g_res[(size_t)n * D0 + t];
    float o = ln + sg * rv;
    float ov = o > 0.f ? o : expm1f(o);
    size_t idx = (size_t)n * D0 + t;
    g_feat[idx] = ov;
    __nv_bfloat16 hi = __float2bfloat16(ov);
    g_ahi[idx] = hi;
    g_alo[idx] = __float2bfloat16(ov - __bfloat162float(hi));
}

// ---------------- layer 2 aggregation ---------------------------------------
__global__ void k_agg2(const float* __restrict__ b2,
                       const float* __restrict__ lng, const float* __restrict__ lnb,
                       const float* __restrict__ rw, float* __restrict__ out) {
    __shared__ float red[9];
    int n = blockIdx.x;
    int c = threadIdx.x;
    int b = g_rowptr[n], e = g_rowptr[n + 1];
    float acc[8] = {0.f, 0.f, 0.f, 0.f, 0.f, 0.f, 0.f, 0.f};
    for (int j = b; j < e; j++) {
        const float* hp = g_h + (size_t)g_col[j] * D2 + c;
        const float* ap = g_alpha + (size_t)j * HEADS;
#pragma unroll
        for (int h = 0; h < 8; h++) acc[h] += ap[h] * hp[h * OUTC];
    }
    float v = (acc[0] + acc[1] + acc[2] + acc[3] + acc[4] + acc[5] + acc[6] + acc[7]) * 0.125f
              + b2[c];
    float s = v, q = v * v;
#pragma unroll
    for (int o = 16; o; o >>= 1) {
        s += __shfl_down_sync(0xffffffffu, s, o);
        q += __shfl_down_sync(0xffffffffu, q, o);
    }
    int w = c >> 5, lane = c & 31;
    if (lane == 0) { red[w] = s; red[4 + w] = q; }
    __syncthreads();
    if (c == 0) {
        float S = 0.f, Q = 0.f;
        for (int i = 0; i < 4; i++) { S += red[i]; Q += red[4 + i]; }
        red[0] = S; red[4] = Q;
    }
    __syncthreads();
    float mu = red[0] * (1.f / 128.f);
    float var = red[4] * (1.f / 128.f) - mu * mu;
    float ln = (v - mu) * rsqrtf(var + 1e-5f) * lng[c] + lnb[c];
    float sg = 1.f / (1.f + expf(-rw[0]));
    out[(size_t)n * OUTC + c] = ln + sg * g_res[(size_t)n * OUTC + c];
}

// ---------------------------------------------------------------------------
extern "C" void kernel_launch(void* const* d_in, const int* in_sizes, int n_in,
                              void* d_out, int out_size) {
    const float* x    = (const float*)d_in[0];
    const void*  ei   = d_in[1];
    const float* W0  = (const float*)d_in[2];
    const float* b0  = (const float*)d_in[3];
    const float* as0 = (const float*)d_in[4];
    const float* ad0 = (const float*)d_in[5];
    const float* lng0 = (const float*)d_in[6];
    const float* lnb0 = (const float*)d_in[7];
    const float* rW0 = (const float*)d_in[8];
    const float* rb0 = (const float*)d_in[9];
    const float* rw0 = (const float*)d_in[10];
    const float* W1  = (const float*)d_in[11];
    const float* b1  = (const float*)d_in[12];
    const float* as1 = (const float*)d_in[13];
    const float* ad1 = (const float*)d_in[14];
    const float* lng1 = (const float*)d_in[15];
    const float* lnb1 = (const float*)d_in[16];
    const float* rw1 = (const float*)d_in[17];
    const float* W2  = (const float*)d_in[18];
    const float* b2  = (const float*)d_in[19];
    const float* as2 = (const float*)d_in[20];
    const float* ad2 = (const float*)d_in[21];
    const float* lng2 = (const float*)d_in[22];
    const float* lnb2 = (const float*)d_in[23];
    const float* rW2 = (const float*)d_in[24];
    const float* rb2 = (const float*)d_in[25];
    const float* rw2 = (const float*)d_in[26];
    float* out = (float*)d_out;

    // ---- CSR build ----
    k_deg_init<<<(NN + 255) / 256, 256>>>();
    k_detect<<<256, 256>>>((const unsigned long long*)ei);
    k_count<<<(EE + 255) / 256, 256>>>(ei);
    k_scanA<<<NPART, 256>>>();
    k_scanB<<<1, 128>>>();
    k_scanC<<<NPART, 256>>>();
    k_fill<<<(TOTE + 255) / 256, 256>>>(ei);

    // ---- weight prep (contiguous packing for merged GEMMs) ----
    k_cvtW<<<(64 * 256 + 255) / 256, 256>>>(W0,  OFF_W0,  64, 256);
    k_cvtW<<<(64 * 256 + 255) / 256, 256>>>(rW0, OFF_RW0, 64, 256);
    k_cvtW<<<(256 * 256 + 255) / 256, 256>>>(W1, OFF_W1, 256, 256);
    k_cvtW<<<(256 * 1024 + 255) / 256, 256>>>(W2, OFF_W2, 256, 1024);
    k_cvtW<<<(256 * 128 + 255) / 256, 256>>>(rW2, OFF_RW2, 256, 128);

    const int GY = (NN + 127) / 128;   // 157

    // ---- layer 0: merged [W0 | rW0] GEMM, coef fused ----
    k_cvtA<<<(NN * 64 + 255) / 256, 256>>>(x, 64);
    k_mma<<<dim3(8, GY), 256>>>(64, OFF_W0, rb0, 256, 256, 256, 1, as0, ad0);
    k_alpha<<<(NN * HEADS + 255) / 256, 256>>>();
    k_agg01<<<NN, 256>>>(b0, lng0, lnb0, 0, rw0);

    // ---- layer 1: coef fused ----
    k_mma<<<dim3(4, GY), 256>>>(256, OFF_W1, nullptr, 256, 256, 256, 1, as1, ad1);
    k_alpha<<<(NN * HEADS + 255) / 256, 256>>>();
    k_agg01<<<NN, 256>>>(b1, lng1, lnb1, 1, rw1);

    // ---- layer 2: merged [W2 | rW2] GEMM ----
    k_mma<<<dim3(18, GY), 256>>>(256, OFF_W2, rb2, 1024, 1024, 128, 0, nullptr, nullptr);
    k_coef<<<(NN * HEADS * 32 + 255) / 256, 256>>>(as2, ad2, D2, OUTC);
    k_alpha<<<(NN * HEADS + 255) / 256, 256>>>();
    k_agg2<<<NN, 128>>>(b2, lng2, lnb2, rw2, out);
}